// round 5
// baseline (speedup 1.0000x reference)
#include <cuda_runtime.h>

// Problem constants
#define BB   64      // batch
#define NN   8192    // nodes
#define DIN  64
#define DOUT 64
#define DD   10      // embedding dim
#define CC   4       // clients
#define NPC  2048    // nodes per client

#define K1_CHUNKS 32
#define K1_NODES  (NN / K1_CHUNKS)   // 256 nodes per chunk

#define NT 8   // nodes per block in main kernel
#define BT 8   // batch tile in main kernel

typedef unsigned long long u64;

// packed f32x2 helpers (FFMA2/FMUL2 path — ptxas never emits these from C++)
__device__ __forceinline__ u64 pk2(float lo, float hi) {
    u64 r; asm("mov.b64 %0,{%1,%2};" : "=l"(r) : "f"(lo), "f"(hi)); return r;
}
__device__ __forceinline__ u64 dup2(float v) { return pk2(v, v); }
__device__ __forceinline__ void f2fma(u64& d, u64 a, u64 b) {
    asm("fma.rn.f32x2 %0,%1,%2,%3;" : "=l"(d) : "l"(a), "l"(b), "l"(d));
}
__device__ __forceinline__ u64 f2mul(u64 a, u64 b) {
    u64 r; asm("mul.rn.f32x2 %0,%1,%2;" : "=l"(r) : "l"(a), "l"(b)); return r;
}
__device__ __forceinline__ float2 u2f(u64 v) {
    float2 f; asm("mov.b64 {%0,%1},%2;" : "=f"(f.x), "=f"(f.y) : "l"(v)); return f;
}

// Scratch (device globals; no runtime allocation allowed)
__device__ float g_part[BB * K1_CHUNKS * DD * DIN];   // 5.2 MB
__device__ float g_sumEH[BB * DD * DIN];              // 160 KB

// ---------------------------------------------------------------------------
// Kernel 1: partial sum_EH[b,chunk,d,i] over chunk nodes of
//           relu(E[g,d]) * (x[b,g,i] * mask[b,g])
// Warp handles 2 nodes per step (16 lanes x float4 = DIN), packed f32x2 math.
// ---------------------------------------------------------------------------
__global__ __launch_bounds__(256) void k1_partial(
    const float* __restrict__ x, const float* __restrict__ emb,
    const float* __restrict__ mask, const int* __restrict__ nodes_per)
{
    __shared__ u64   s_tE[K1_NODES * DD];   // dup'd relu(E): 20 KB
    __shared__ int   s_g[K1_NODES];          // 1 KB
    __shared__ float s_red[8][DD * DIN];     // 20 KB

    const int t = threadIdx.x;
    const int b = blockIdx.y, chunk = blockIdx.x;
    const int p0 = chunk * K1_NODES;

    for (int p = t; p < K1_NODES; p += 256) s_g[p] = nodes_per[p0 + p];
    __syncthreads();
    for (int e = t; e < K1_NODES * DD; e += 256) {
        int p = e / DD, d = e - p * DD;
        s_tE[e] = dup2(fmaxf(emb[(size_t)s_g[p] * DD + d], 0.f));
    }
    __syncthreads();

    const int w = t >> 5, lane = t & 31;
    const int il = lane & 15, np = lane >> 4;   // i-block, node parity

    u64 acc[DD][2];
#pragma unroll
    for (int d = 0; d < DD; d++) { acc[d][0] = 0ull; acc[d][1] = 0ull; }

    const float* xb = x + (size_t)b * NN * DIN;
    const float* mb = mask + (size_t)b * NN;
    const int base = w * (K1_NODES / 8);   // 32 nodes per warp

#pragma unroll 1
    for (int j = 0; j < K1_NODES / 8; j += 4) {
        // two node-pairs prefetched; this thread covers parity np of each pair
        int pA = base + j + np, pB = base + j + 2 + np;
        int gA = s_g[pA], gB = s_g[pB];
        float mA = __ldg(&mb[gA]), mB = __ldg(&mb[gB]);
        float4 xA = *(const float4*)(xb + (size_t)gA * DIN + il * 4);
        float4 xB = *(const float4*)(xb + (size_t)gB * DIN + il * 4);

        {
            u64 md = dup2(mA);
            u64 z01 = f2mul(pk2(xA.x, xA.y), md);
            u64 z23 = f2mul(pk2(xA.z, xA.w), md);
            const u64* te = &s_tE[pA * DD];
#pragma unroll
            for (int d = 0; d < DD; d++) {
                u64 e = te[d];
                f2fma(acc[d][0], e, z01);
                f2fma(acc[d][1], e, z23);
            }
        }
        {
            u64 md = dup2(mB);
            u64 z01 = f2mul(pk2(xB.x, xB.y), md);
            u64 z23 = f2mul(pk2(xB.z, xB.w), md);
            const u64* te = &s_tE[pB * DD];
#pragma unroll
            for (int d = 0; d < DD; d++) {
                u64 e = te[d];
                f2fma(acc[d][0], e, z01);
                f2fma(acc[d][1], e, z23);
            }
        }
    }

    // reduce across node-parity halves, then write per-warp slice
#pragma unroll
    for (int d = 0; d < DD; d++) {
        float2 v0 = u2f(acc[d][0]), v1 = u2f(acc[d][1]);
        v0.x += __shfl_xor_sync(0xffffffffu, v0.x, 16);
        v0.y += __shfl_xor_sync(0xffffffffu, v0.y, 16);
        v1.x += __shfl_xor_sync(0xffffffffu, v1.x, 16);
        v1.y += __shfl_xor_sync(0xffffffffu, v1.y, 16);
        if (np == 0)
            *(float4*)&s_red[w][d * DIN + il * 4] = make_float4(v0.x, v0.y, v1.x, v1.y);
    }
    __syncthreads();
    for (int di = t; di < DD * DIN; di += 256) {
        float s = 0.f;
#pragma unroll
        for (int w2 = 0; w2 < 8; w2++) s += s_red[w2][di];
        g_part[((size_t)b * K1_CHUNKS + chunk) * (DD * DIN) + di] = s;
    }
}

// ---------------------------------------------------------------------------
// Kernel 2: reduce chunk partials -> g_sumEH[b,d,i]
// ---------------------------------------------------------------------------
__global__ __launch_bounds__(256) void k2_reduce()
{
    int idx = blockIdx.x * 256 + threadIdx.x;
    if (idx >= BB * DD * DIN) return;
    int b = idx / (DD * DIN), di = idx - b * (DD * DIN);
    float s = 0.f;
#pragma unroll
    for (int k = 0; k < K1_CHUNKS; k++)
        s += g_part[((size_t)b * K1_CHUNKS + k) * (DD * DIN) + di];
    g_sumEH[idx] = s;
}

// ---------------------------------------------------------------------------
// Kernel 3: fused main kernel, 512 threads/block, 2 warps per node.
// Z stored PRE-DUPLICATED in smem so GEMM inner loop is LDS->FFMA2 only.
// ---------------------------------------------------------------------------
struct Smem3 {
    float sW[NT * DIN * DOUT];     // 131072 B  [nt][k][o]
    u64   sZ[BT * NT * DIN];       // 32768 B   [bb][nt][k] (dup'd pairs)
    float sSum[BT * DD * DIN];     // 20480 B   [bb][d][i]
    float sE[NT * DD];
    float sbb[NT * DOUT];
    int   sIdx[NT];
};                                  // ~186.6 KB

__global__ __launch_bounds__(512, 1) void k3_main(
    const float* __restrict__ x, const float* __restrict__ emb,
    const float* __restrict__ mask, const float* __restrict__ wpool,
    const float* __restrict__ bpool, const int* __restrict__ nodes_per,
    float* __restrict__ out)
{
    extern __shared__ __align__(16) char smem_raw[];
    Smem3& S = *reinterpret_cast<Smem3*>(smem_raw);

    const int t = threadIdx.x;
    const int node0 = blockIdx.x * NT;
    const int c = node0 / NPC;

    if (t < NT) S.sIdx[t] = nodes_per[node0 + t];
    __syncthreads();
    if (t < NT * DD) {
        int nt = t / DD, d = t - nt * DD;
        S.sE[t] = emb[(size_t)S.sIdx[nt] * DD + d];
    }
    __syncthreads();

    // bias: 512 threads cover NT*DOUT = 512 exactly
    {
        int nt = t >> 6, o = t & 63;
        float s = 0.f;
#pragma unroll
        for (int d = 0; d < DD; d++)
            s = fmaf(S.sE[nt * DD + d], bpool[((size_t)c * DD + d) * DOUT + o], s);
        S.sbb[t] = s;
    }

    // W generation (packed): thread owns 4 consecutive floats per pg (2 pgs).
    const float* wpc = wpool + (size_t)c * DD * DIN * DOUT;
#pragma unroll
    for (int pg = 0; pg < 2; pg++) {
        u64 acc[2][NT];
#pragma unroll
        for (int h = 0; h < 2; h++)
#pragma unroll
            for (int nt = 0; nt < NT; nt++) acc[h][nt] = 0ull;
#pragma unroll
        for (int d = 0; d < DD; d++) {
            ulonglong2 wp = *(const ulonglong2*)&wpc[(size_t)d * (DIN * DOUT) + pg * 2048 + t * 4];
#pragma unroll
            for (int nt = 0; nt < NT; nt++) {
                u64 ed = dup2(S.sE[nt * DD + d]);
                f2fma(acc[0][nt], wp.x, ed);
                f2fma(acc[1][nt], wp.y, ed);
            }
        }
#pragma unroll
        for (int nt = 0; nt < NT; nt++) {
            *(float2*)&S.sW[nt * (DIN * DOUT) + pg * 2048 + t * 4]     = u2f(acc[0][nt]);
            *(float2*)&S.sW[nt * (DIN * DOUT) + pg * 2048 + t * 4 + 2] = u2f(acc[1][nt]);
        }
    }
    __syncthreads();

    const int nt = t >> 6;         // node within block (2 warps per node)
    const int tid64 = t & 63;
    const int g = S.sIdx[nt];

    // Z-gen mapping: 32 i-pairs x 2 bb-halves
    const int i2  = (tid64 & 31) * 2;
    const int bbh = tid64 >> 5;

    // GEMM mapping: 16 o-groups x 4 bb-groups
    const int o0  = (tid64 & 15) * 4;
    const int bb0 = (tid64 >> 4) * 2;

    // hoisted packed relu(E[nt,:]) for Z-gen
    u64 edup[DD];
#pragma unroll
    for (int d = 0; d < DD; d++) edup[d] = dup2(fmaxf(S.sE[nt * DD + d], 0.f));

    for (int bt = 0; bt < BB / BT; bt++) {
        const int b0 = bt * BT;
        for (int e = t; e < BT * DD * DIN; e += 512)
            S.sSum[e] = g_sumEH[(size_t)(b0 + e / (DD * DIN)) * (DD * DIN) + e % (DD * DIN)];
        __syncthreads();

        // Z-gen: thread covers 4 batches at its i-pair; stores DUP'D pairs
#pragma unroll
        for (int j = 0; j < 4; j++) {
            int bb = bbh * 4 + j;
            int b = b0 + bb;
            float m = mask[(size_t)b * NN + g];
            float2 xv = *(const float2*)(x + ((size_t)b * NN + g) * DIN + i2);
            u64 z = pk2(xv.x * m, xv.y * m);
#pragma unroll
            for (int d = 0; d < DD; d++) {
                u64 sv = *(const u64*)&S.sSum[(bb * DD + d) * DIN + i2];
                f2fma(z, edup[d], sv);
            }
            float2 zf = u2f(z);
            ulonglong2 zz; zz.x = dup2(zf.x); zz.y = dup2(zf.y);
            *(ulonglong2*)&S.sZ[(bb * NT + nt) * DIN + i2] = zz;
        }
        __syncthreads();

        // GEMM: 2 bb x 4 o per thread; pure LDS->FFMA2 inner loop
        u64 acc00, acc01, acc10, acc11;
        {
            ulonglong2 bv = *(const ulonglong2*)&S.sbb[nt * DOUT + o0];
            acc00 = bv.x; acc01 = bv.y; acc10 = bv.x; acc11 = bv.y;
        }
        const u64* zA = &S.sZ[(bb0 * NT + nt) * DIN];
        const u64* zB = &S.sZ[((bb0 + 1) * NT + nt) * DIN];
        const float* wrow = &S.sW[nt * (DIN * DOUT) + o0];
#pragma unroll
        for (int k = 0; k < DIN; k += 2) {
            ulonglong2 w0 = *(const ulonglong2*)(wrow + (size_t)k * DOUT);
            ulonglong2 w1 = *(const ulonglong2*)(wrow + (size_t)(k + 1) * DOUT);
            u64 za0 = zA[k], za1 = zA[k + 1];
            u64 zb0 = zB[k], zb1 = zB[k + 1];
            f2fma(acc00, za0, w0.x); f2fma(acc01, za0, w0.y);
            f2fma(acc10, zb0, w0.x); f2fma(acc11, zb0, w0.y);
            f2fma(acc00, za1, w1.x); f2fma(acc01, za1, w1.y);
            f2fma(acc10, zb1, w1.x); f2fma(acc11, zb1, w1.y);
        }
        {
            float2 p0 = u2f(acc00), p1 = u2f(acc01);
            *(float4*)(out + ((size_t)(b0 + bb0) * NN + node0 + nt) * DOUT + o0) =
                make_float4(p0.x, p0.y, p1.x, p1.y);
            float2 q0 = u2f(acc10), q1 = u2f(acc11);
            *(float4*)(out + ((size_t)(b0 + bb0 + 1) * NN + node0 + nt) * DOUT + o0) =
                make_float4(q0.x, q0.y, q1.x, q1.y);
        }
        __syncthreads();
    }
}

// ---------------------------------------------------------------------------
extern "C" void kernel_launch(void* const* d_in, const int* in_sizes, int n_in,
                              void* d_out, int out_size)
{
    const float* x     = (const float*)d_in[0];
    const float* emb   = (const float*)d_in[1];
    // d_in[2] = poly_coefficients (unused in sprtrelu mode)
    const float* mask  = (const float*)d_in[3];
    const float* wpool = (const float*)d_in[4];
    const float* bpool = (const float*)d_in[5];
    const int*   nodes = (const int*)d_in[6];
    float* out = (float*)d_out;

    cudaFuncSetAttribute(k3_main, cudaFuncAttributeMaxDynamicSharedMemorySize,
                         (int)sizeof(Smem3));

    dim3 g1(K1_CHUNKS, BB);
    k1_partial<<<g1, 256>>>(x, emb, mask, nodes);

    int tot = BB * DD * DIN;
    k2_reduce<<<(tot + 255) / 256, 256>>>();

    k3_main<<<NN / NT, 512, sizeof(Smem3)>>>(x, emb, mask, wpool, bpool, nodes, out);
}

// round 6
// speedup vs baseline: 1.0095x; 1.0095x over previous
#include <cuda_runtime.h>

// Problem constants
#define BB   64      // batch
#define NN   8192    // nodes
#define DIN  64
#define DOUT 64
#define DD   10      // embedding dim
#define CC   4       // clients
#define NPC  2048    // nodes per client

#define K1_CHUNKS 32
#define K1_NODES  (NN / K1_CHUNKS)   // 256 nodes per chunk

#define NT 8   // nodes per block in main kernel
#define BT 8   // batch tile in main kernel

typedef unsigned long long u64;

// packed f32x2 helpers (FFMA2/FMUL2 path — ptxas never emits these from C++)
__device__ __forceinline__ u64 pk2(float lo, float hi) {
    u64 r; asm("mov.b64 %0,{%1,%2};" : "=l"(r) : "f"(lo), "f"(hi)); return r;
}
__device__ __forceinline__ u64 dup2(float v) { return pk2(v, v); }
__device__ __forceinline__ void f2fma(u64& d, u64 a, u64 b) {
    asm("fma.rn.f32x2 %0,%1,%2,%3;" : "=l"(d) : "l"(a), "l"(b), "l"(d));
}
__device__ __forceinline__ u64 f2mul(u64 a, u64 b) {
    u64 r; asm("mul.rn.f32x2 %0,%1,%2;" : "=l"(r) : "l"(a), "l"(b)); return r;
}
__device__ __forceinline__ float2 u2f(u64 v) {
    float2 f; asm("mov.b64 {%0,%1},%2;" : "=f"(f.x), "=f"(f.y) : "l"(v)); return f;
}

// Scratch (device globals; no runtime allocation allowed)
__device__ float g_part[BB * K1_CHUNKS * DD * DIN];   // 5.2 MB
__device__ float g_sumEH[BB * DD * DIN];              // 160 KB

// ---------------------------------------------------------------------------
// Kernel 1: partial sum_EH[b,chunk,d,i] over chunk nodes of
//           relu(E[g,d]) * (x[b,g,i] * mask[b,g])
// Warp handles 2 nodes per step (16 lanes x float4 = DIN), packed f32x2 math.
// ---------------------------------------------------------------------------
__global__ __launch_bounds__(256) void k1_partial(
    const float* __restrict__ x, const float* __restrict__ emb,
    const float* __restrict__ mask, const int* __restrict__ nodes_per)
{
    __shared__ u64   s_tE[K1_NODES * DD];   // dup'd relu(E): 20 KB
    __shared__ int   s_g[K1_NODES];          // 1 KB
    __shared__ float s_red[8][DD * DIN];     // 20 KB

    const int t = threadIdx.x;
    const int b = blockIdx.y, chunk = blockIdx.x;
    const int p0 = chunk * K1_NODES;

    for (int p = t; p < K1_NODES; p += 256) s_g[p] = nodes_per[p0 + p];
    __syncthreads();
    for (int e = t; e < K1_NODES * DD; e += 256) {
        int p = e / DD, d = e - p * DD;
        s_tE[e] = dup2(fmaxf(emb[(size_t)s_g[p] * DD + d], 0.f));
    }
    __syncthreads();

    const int w = t >> 5, lane = t & 31;
    const int il = lane & 15, np = lane >> 4;   // i-block, node parity

    u64 acc[DD][2];
#pragma unroll
    for (int d = 0; d < DD; d++) { acc[d][0] = 0ull; acc[d][1] = 0ull; }

    const float* xb = x + (size_t)b * NN * DIN;
    const float* mb = mask + (size_t)b * NN;
    const int base = w * (K1_NODES / 8);   // 32 nodes per warp

#pragma unroll 1
    for (int j = 0; j < K1_NODES / 8; j += 4) {
        // two node-pairs prefetched; this thread covers parity np of each pair
        int pA = base + j + np, pB = base + j + 2 + np;
        int gA = s_g[pA], gB = s_g[pB];
        float mA = __ldg(&mb[gA]), mB = __ldg(&mb[gB]);
        float4 xA = *(const float4*)(xb + (size_t)gA * DIN + il * 4);
        float4 xB = *(const float4*)(xb + (size_t)gB * DIN + il * 4);

        {
            u64 md = dup2(mA);
            u64 z01 = f2mul(pk2(xA.x, xA.y), md);
            u64 z23 = f2mul(pk2(xA.z, xA.w), md);
            const u64* te = &s_tE[pA * DD];
#pragma unroll
            for (int d = 0; d < DD; d++) {
                u64 e = te[d];
                f2fma(acc[d][0], e, z01);
                f2fma(acc[d][1], e, z23);
            }
        }
        {
            u64 md = dup2(mB);
            u64 z01 = f2mul(pk2(xB.x, xB.y), md);
            u64 z23 = f2mul(pk2(xB.z, xB.w), md);
            const u64* te = &s_tE[pB * DD];
#pragma unroll
            for (int d = 0; d < DD; d++) {
                u64 e = te[d];
                f2fma(acc[d][0], e, z01);
                f2fma(acc[d][1], e, z23);
            }
        }
    }

    // reduce across node-parity halves, then write per-warp slice
#pragma unroll
    for (int d = 0; d < DD; d++) {
        float2 v0 = u2f(acc[d][0]), v1 = u2f(acc[d][1]);
        v0.x += __shfl_xor_sync(0xffffffffu, v0.x, 16);
        v0.y += __shfl_xor_sync(0xffffffffu, v0.y, 16);
        v1.x += __shfl_xor_sync(0xffffffffu, v1.x, 16);
        v1.y += __shfl_xor_sync(0xffffffffu, v1.y, 16);
        if (np == 0)
            *(float4*)&s_red[w][d * DIN + il * 4] = make_float4(v0.x, v0.y, v1.x, v1.y);
    }
    __syncthreads();
    for (int di = t; di < DD * DIN; di += 256) {
        float s = 0.f;
#pragma unroll
        for (int w2 = 0; w2 < 8; w2++) s += s_red[w2][di];
        g_part[((size_t)b * K1_CHUNKS + chunk) * (DD * DIN) + di] = s;
    }
}

// ---------------------------------------------------------------------------
// Kernel 2: reduce chunk partials -> g_sumEH[b,d,i]
// ---------------------------------------------------------------------------
__global__ __launch_bounds__(256) void k2_reduce()
{
    int idx = blockIdx.x * 256 + threadIdx.x;
    if (idx >= BB * DD * DIN) return;
    int b = idx / (DD * DIN), di = idx - b * (DD * DIN);
    float s = 0.f;
#pragma unroll
    for (int k = 0; k < K1_CHUNKS; k++)
        s += g_part[((size_t)b * K1_CHUNKS + k) * (DD * DIN) + di];
    g_sumEH[idx] = s;
}

// ---------------------------------------------------------------------------
// Kernel 3: fused main kernel, 512 threads/block, 2 warps per node.
// Z stored PRE-DUPLICATED in smem so GEMM inner loop is LDS->FFMA2 only.
// ---------------------------------------------------------------------------
struct Smem3 {
    float sW[NT * DIN * DOUT];     // 131072 B  [nt][k][o]
    u64   sZ[BT * NT * DIN];       // 32768 B   [bb][nt][k] (dup'd pairs)
    float sSum[BT * DD * DIN];     // 20480 B   [bb][d][i]
    float sE[NT * DD];
    float sbb[NT * DOUT];
    int   sIdx[NT];
};                                  // ~186.6 KB

__global__ __launch_bounds__(512, 1) void k3_main(
    const float* __restrict__ x, const float* __restrict__ emb,
    const float* __restrict__ mask, const float* __restrict__ wpool,
    const float* __restrict__ bpool, const int* __restrict__ nodes_per,
    float* __restrict__ out)
{
    extern __shared__ __align__(16) char smem_raw[];
    Smem3& S = *reinterpret_cast<Smem3*>(smem_raw);

    const int t = threadIdx.x;
    const int node0 = blockIdx.x * NT;
    const int c = node0 / NPC;

    if (t < NT) S.sIdx[t] = nodes_per[node0 + t];
    __syncthreads();
    if (t < NT * DD) {
        int nt = t / DD, d = t - nt * DD;
        S.sE[t] = emb[(size_t)S.sIdx[nt] * DD + d];
    }
    __syncthreads();

    // bias: 512 threads cover NT*DOUT = 512 exactly
    {
        int nt = t >> 6, o = t & 63;
        float s = 0.f;
#pragma unroll
        for (int d = 0; d < DD; d++)
            s = fmaf(S.sE[nt * DD + d], bpool[((size_t)c * DD + d) * DOUT + o], s);
        S.sbb[t] = s;
    }

    // W generation (packed): thread owns 4 consecutive floats per pg (2 pgs).
    const float* wpc = wpool + (size_t)c * DD * DIN * DOUT;
#pragma unroll
    for (int pg = 0; pg < 2; pg++) {
        u64 acc[2][NT];
#pragma unroll
        for (int h = 0; h < 2; h++)
#pragma unroll
            for (int nt = 0; nt < NT; nt++) acc[h][nt] = 0ull;
#pragma unroll
        for (int d = 0; d < DD; d++) {
            ulonglong2 wp = *(const ulonglong2*)&wpc[(size_t)d * (DIN * DOUT) + pg * 2048 + t * 4];
#pragma unroll
            for (int nt = 0; nt < NT; nt++) {
                u64 ed = dup2(S.sE[nt * DD + d]);
                f2fma(acc[0][nt], wp.x, ed);
                f2fma(acc[1][nt], wp.y, ed);
            }
        }
#pragma unroll
        for (int nt = 0; nt < NT; nt++) {
            *(float2*)&S.sW[nt * (DIN * DOUT) + pg * 2048 + t * 4]     = u2f(acc[0][nt]);
            *(float2*)&S.sW[nt * (DIN * DOUT) + pg * 2048 + t * 4 + 2] = u2f(acc[1][nt]);
        }
    }
    __syncthreads();

    const int nt = t >> 6;         // node within block (2 warps per node)
    const int tid64 = t & 63;
    const int g = S.sIdx[nt];

    // Z-gen mapping: 32 i-pairs x 2 bb-halves
    const int i2  = (tid64 & 31) * 2;
    const int bbh = tid64 >> 5;

    // GEMM mapping: 16 o-groups x 4 bb-groups
    const int o0  = (tid64 & 15) * 4;
    const int bb0 = (tid64 >> 4) * 2;

    // hoisted packed relu(E[nt,:]) for Z-gen
    u64 edup[DD];
#pragma unroll
    for (int d = 0; d < DD; d++) edup[d] = dup2(fmaxf(S.sE[nt * DD + d], 0.f));

    for (int bt = 0; bt < BB / BT; bt++) {
        const int b0 = bt * BT;
        for (int e = t; e < BT * DD * DIN; e += 512)
            S.sSum[e] = g_sumEH[(size_t)(b0 + e / (DD * DIN)) * (DD * DIN) + e % (DD * DIN)];
        __syncthreads();

        // Z-gen: thread covers 4 batches at its i-pair; stores DUP'D pairs
#pragma unroll
        for (int j = 0; j < 4; j++) {
            int bb = bbh * 4 + j;
            int b = b0 + bb;
            float m = mask[(size_t)b * NN + g];
            float2 xv = *(const float2*)(x + ((size_t)b * NN + g) * DIN + i2);
            u64 z = pk2(xv.x * m, xv.y * m);
#pragma unroll
            for (int d = 0; d < DD; d++) {
                u64 sv = *(const u64*)&S.sSum[(bb * DD + d) * DIN + i2];
                f2fma(z, edup[d], sv);
            }
            float2 zf = u2f(z);
            ulonglong2 zz; zz.x = dup2(zf.x); zz.y = dup2(zf.y);
            *(ulonglong2*)&S.sZ[(bb * NT + nt) * DIN + i2] = zz;
        }
        __syncthreads();

        // GEMM: 2 bb x 4 o per thread; pure LDS->FFMA2 inner loop
        u64 acc00, acc01, acc10, acc11;
        {
            ulonglong2 bv = *(const ulonglong2*)&S.sbb[nt * DOUT + o0];
            acc00 = bv.x; acc01 = bv.y; acc10 = bv.x; acc11 = bv.y;
        }
        const u64* zA = &S.sZ[(bb0 * NT + nt) * DIN];
        const u64* zB = &S.sZ[((bb0 + 1) * NT + nt) * DIN];
        const float* wrow = &S.sW[nt * (DIN * DOUT) + o0];
#pragma unroll
        for (int k = 0; k < DIN; k += 2) {
            ulonglong2 w0 = *(const ulonglong2*)(wrow + (size_t)k * DOUT);
            ulonglong2 w1 = *(const ulonglong2*)(wrow + (size_t)(k + 1) * DOUT);
            u64 za0 = zA[k], za1 = zA[k + 1];
            u64 zb0 = zB[k], zb1 = zB[k + 1];
            f2fma(acc00, za0, w0.x); f2fma(acc01, za0, w0.y);
            f2fma(acc10, zb0, w0.x); f2fma(acc11, zb0, w0.y);
            f2fma(acc00, za1, w1.x); f2fma(acc01, za1, w1.y);
            f2fma(acc10, zb1, w1.x); f2fma(acc11, zb1, w1.y);
        }
        {
            float2 p0 = u2f(acc00), p1 = u2f(acc01);
            *(float4*)(out + ((size_t)(b0 + bb0) * NN + node0 + nt) * DOUT + o0) =
                make_float4(p0.x, p0.y, p1.x, p1.y);
            float2 q0 = u2f(acc10), q1 = u2f(acc11);
            *(float4*)(out + ((size_t)(b0 + bb0 + 1) * NN + node0 + nt) * DOUT + o0) =
                make_float4(q0.x, q0.y, q1.x, q1.y);
        }
        __syncthreads();
    }
}

// ---------------------------------------------------------------------------
extern "C" void kernel_launch(void* const* d_in, const int* in_sizes, int n_in,
                              void* d_out, int out_size)
{
    const float* x     = (const float*)d_in[0];
    const float* emb   = (const float*)d_in[1];
    // d_in[2] = poly_coefficients (unused in sprtrelu mode)
    const float* mask  = (const float*)d_in[3];
    const float* wpool = (const float*)d_in[4];
    const float* bpool = (const float*)d_in[5];
    const int*   nodes = (const int*)d_in[6];
    float* out = (float*)d_out;

    cudaFuncSetAttribute(k3_main, cudaFuncAttributeMaxDynamicSharedMemorySize,
                         (int)sizeof(Smem3));

    dim3 g1(K1_CHUNKS, BB);
    k1_partial<<<g1, 256>>>(x, emb, mask, nodes);

    int tot = BB * DD * DIN;
    k2_reduce<<<(tot + 255) / 256, 256>>>();

    k3_main<<<NN / NT, 512, sizeof(Smem3)>>>(x, emb, mask, wpool, bpool, nodes, out);
}

// round 7
// speedup vs baseline: 1.0807x; 1.0705x over previous
#include <cuda_runtime.h>

// Problem constants
#define BB   64      // batch
#define NN   8192    // nodes
#define DIN  64
#define DOUT 64
#define DD   10      // embedding dim
#define CC   4       // clients
#define NPC  2048    // nodes per client

#define K1_CHUNKS 32
#define K1_NODES  (NN / K1_CHUNKS)   // 256 nodes per chunk

#define NT 4   // nodes per block in main kernel (smem ~104KB -> 2 CTA/SM)
#define BT 8   // batch tile in main kernel

typedef unsigned long long u64;

// packed f32x2 helpers (FFMA2/FMUL2 path — ptxas never emits these from C++)
__device__ __forceinline__ u64 pk2(float lo, float hi) {
    u64 r; asm("mov.b64 %0,{%1,%2};" : "=l"(r) : "f"(lo), "f"(hi)); return r;
}
__device__ __forceinline__ u64 dup2(float v) { return pk2(v, v); }
__device__ __forceinline__ void f2fma(u64& d, u64 a, u64 b) {
    asm("fma.rn.f32x2 %0,%1,%2,%3;" : "=l"(d) : "l"(a), "l"(b), "l"(d));
}
__device__ __forceinline__ u64 f2mul(u64 a, u64 b) {
    u64 r; asm("mul.rn.f32x2 %0,%1,%2;" : "=l"(r) : "l"(a), "l"(b)); return r;
}
__device__ __forceinline__ float2 u2f(u64 v) {
    float2 f; asm("mov.b64 {%0,%1},%2;" : "=f"(f.x), "=f"(f.y) : "l"(v)); return f;
}

// Scratch (device globals; no runtime allocation allowed)
__device__ float g_part[BB * K1_CHUNKS * DD * DIN];   // 5.2 MB
__device__ float g_sumEH[BB * DD * DIN];              // 160 KB

// ---------------------------------------------------------------------------
// Kernel 1: partial sum_EH[b,chunk,d,i] over chunk nodes of
//           relu(E[g,d]) * (x[b,g,i] * mask[b,g])
// Warp handles 8 nodes per step (16 lanes x float4 = DIN, 2 node parities),
// 4 x-row LDG.128 in flight per thread. Packed f32x2 math.
// ---------------------------------------------------------------------------
__global__ __launch_bounds__(256) void k1_partial(
    const float* __restrict__ x, const float* __restrict__ emb,
    const float* __restrict__ mask, const int* __restrict__ nodes_per)
{
    __shared__ u64   s_tE[K1_NODES * DD];   // dup'd relu(E): 20 KB
    __shared__ int   s_g[K1_NODES];          // 1 KB
    __shared__ float s_red[8][DD * DIN];     // 20 KB

    const int t = threadIdx.x;
    const int b = blockIdx.y, chunk = blockIdx.x;
    const int p0 = chunk * K1_NODES;

    for (int p = t; p < K1_NODES; p += 256) s_g[p] = nodes_per[p0 + p];
    __syncthreads();
    for (int e = t; e < K1_NODES * DD; e += 256) {
        int p = e / DD, d = e - p * DD;
        s_tE[e] = dup2(fmaxf(emb[(size_t)s_g[p] * DD + d], 0.f));
    }
    __syncthreads();

    const int w = t >> 5, lane = t & 31;
    const int il = lane & 15, np = lane >> 4;   // i-block, node parity

    u64 acc[DD][2];
#pragma unroll
    for (int d = 0; d < DD; d++) { acc[d][0] = 0ull; acc[d][1] = 0ull; }

    const float* xb = x + (size_t)b * NN * DIN;
    const float* mb = mask + (size_t)b * NN;
    const int base = w * (K1_NODES / 8);   // 32 nodes per warp

#pragma unroll 1
    for (int j = 0; j < K1_NODES / 8; j += 8) {
        // 4 node-pair groups prefetched; thread covers parity np of each
        int p4[4]; float m4[4]; float4 x4[4];
#pragma unroll
        for (int q = 0; q < 4; q++) p4[q] = base + j + 2 * q + np;
        int g4[4];
#pragma unroll
        for (int q = 0; q < 4; q++) g4[q] = s_g[p4[q]];
#pragma unroll
        for (int q = 0; q < 4; q++) {
            m4[q] = __ldg(&mb[g4[q]]);
            x4[q] = *(const float4*)(xb + (size_t)g4[q] * DIN + il * 4);
        }
#pragma unroll
        for (int q = 0; q < 4; q++) {
            u64 md = dup2(m4[q]);
            u64 z01 = f2mul(pk2(x4[q].x, x4[q].y), md);
            u64 z23 = f2mul(pk2(x4[q].z, x4[q].w), md);
            const u64* te = &s_tE[p4[q] * DD];
#pragma unroll
            for (int d = 0; d < DD; d++) {
                u64 e = te[d];
                f2fma(acc[d][0], e, z01);
                f2fma(acc[d][1], e, z23);
            }
        }
    }

    // reduce across node-parity halves, then write per-warp slice
#pragma unroll
    for (int d = 0; d < DD; d++) {
        float2 v0 = u2f(acc[d][0]), v1 = u2f(acc[d][1]);
        v0.x += __shfl_xor_sync(0xffffffffu, v0.x, 16);
        v0.y += __shfl_xor_sync(0xffffffffu, v0.y, 16);
        v1.x += __shfl_xor_sync(0xffffffffu, v1.x, 16);
        v1.y += __shfl_xor_sync(0xffffffffu, v1.y, 16);
        if (np == 0)
            *(float4*)&s_red[w][d * DIN + il * 4] = make_float4(v0.x, v0.y, v1.x, v1.y);
    }
    __syncthreads();
    for (int di = t; di < DD * DIN; di += 256) {
        float s = 0.f;
#pragma unroll
        for (int w2 = 0; w2 < 8; w2++) s += s_red[w2][di];
        g_part[((size_t)b * K1_CHUNKS + chunk) * (DD * DIN) + di] = s;
    }
}

// ---------------------------------------------------------------------------
// Kernel 2: reduce chunk partials -> g_sumEH[b,d,i]
// ---------------------------------------------------------------------------
__global__ __launch_bounds__(256) void k2_reduce()
{
    int idx = blockIdx.x * 256 + threadIdx.x;
    if (idx >= BB * DD * DIN) return;
    int b = idx / (DD * DIN), di = idx - b * (DD * DIN);
    float s = 0.f;
#pragma unroll
    for (int k = 0; k < K1_CHUNKS; k++)
        s += g_part[((size_t)b * K1_CHUNKS + k) * (DD * DIN) + di];
    g_sumEH[idx] = s;
}

// ---------------------------------------------------------------------------
// Kernel 3: fused main kernel. 256 threads, NT=4 nodes/block, 2 CTAs/SM.
// Z stored PRE-DUPLICATED in smem so GEMM inner loop is LDS->FFMA2 only.
// sSum register-pipelined across bt iterations.
// ---------------------------------------------------------------------------
struct Smem3 {
    float sW[NT * DIN * DOUT];     // 65536 B  [nt][k][o]
    u64   sZ[BT * NT * DIN];       // 16384 B  [bb][nt][k] (dup'd pairs)
    float sSum[BT * DD * DIN];     // 20480 B  [bb][d][i]
    float sE[NT * DD];
    float sbb[NT * DOUT];
    int   sIdx[NT];
};                                  // ~103.7 KB -> 2 CTAs/SM

__global__ __launch_bounds__(256, 2) void k3_main(
    const float* __restrict__ x, const float* __restrict__ emb,
    const float* __restrict__ mask, const float* __restrict__ wpool,
    const float* __restrict__ bpool, const int* __restrict__ nodes_per,
    float* __restrict__ out)
{
    extern __shared__ __align__(16) char smem_raw[];
    Smem3& S = *reinterpret_cast<Smem3*>(smem_raw);

    const int t = threadIdx.x;
    const int node0 = blockIdx.x * NT;
    const int c = node0 / NPC;

    if (t < NT) S.sIdx[t] = nodes_per[node0 + t];
    __syncthreads();
    if (t < NT * DD) {
        int nt = t / DD, d = t - nt * DD;
        S.sE[t] = emb[(size_t)S.sIdx[nt] * DD + d];
    }
    __syncthreads();

    // kick off first sSum tile load (bt=0) early
    float4 pre[5];
#pragma unroll
    for (int q = 0; q < 5; q++)
        pre[q] = *(const float4*)&g_sumEH[q * 1024 + t * 4];

    // bias: 256 threads cover NT*DOUT = 256 exactly
    {
        int nt = t >> 6, o = t & 63;
        float s = 0.f;
#pragma unroll
        for (int d = 0; d < DD; d++)
            s = fmaf(S.sE[nt * DD + d], bpool[((size_t)c * DD + d) * DOUT + o], s);
        S.sbb[t] = s;
    }

    // W generation (packed): thread owns 4 consecutive floats per pg (4 pgs).
    const float* wpc = wpool + (size_t)c * DD * DIN * DOUT;
#pragma unroll
    for (int pg = 0; pg < 4; pg++) {
        u64 acc[2][NT];
#pragma unroll
        for (int h = 0; h < 2; h++)
#pragma unroll
            for (int nt = 0; nt < NT; nt++) acc[h][nt] = 0ull;
#pragma unroll
        for (int d = 0; d < DD; d++) {
            ulonglong2 wp = *(const ulonglong2*)&wpc[(size_t)d * (DIN * DOUT) + pg * 1024 + t * 4];
#pragma unroll
            for (int nt = 0; nt < NT; nt++) {
                u64 ed = dup2(S.sE[nt * DD + d]);
                f2fma(acc[0][nt], wp.x, ed);
                f2fma(acc[1][nt], wp.y, ed);
            }
        }
#pragma unroll
        for (int nt = 0; nt < NT; nt++) {
            *(float2*)&S.sW[nt * (DIN * DOUT) + pg * 1024 + t * 4]     = u2f(acc[0][nt]);
            *(float2*)&S.sW[nt * (DIN * DOUT) + pg * 1024 + t * 4 + 2] = u2f(acc[1][nt]);
        }
    }

    const int nt = t >> 6;         // node within block (2 warps per node)
    const int tid64 = t & 63;
    const int g = S.sIdx[nt];

    // Z-gen mapping: 32 i-pairs x 2 bb-halves
    const int i2  = (tid64 & 31) * 2;
    const int bbh = tid64 >> 5;

    // GEMM mapping: 16 o-groups x 4 bb-groups
    const int o0  = (tid64 & 15) * 4;
    const int bb0 = (tid64 >> 4) * 2;

    // hoisted packed relu(E[nt,:]) for Z-gen
    u64 edup[DD];
#pragma unroll
    for (int d = 0; d < DD; d++) edup[d] = dup2(fmaxf(S.sE[nt * DD + d], 0.f));

    __syncthreads();   // sW/sbb ready

    for (int bt = 0; bt < BB / BT; bt++) {
        const int b0 = bt * BT;
        // publish prefetched sSum tile
#pragma unroll
        for (int q = 0; q < 5; q++)
            *(float4*)&S.sSum[q * 1024 + t * 4] = pre[q];
        __syncthreads();

        // prefetch next tile into registers (latency hidden by Z-gen + GEMM)
        if (bt + 1 < BB / BT) {
            const float* src = &g_sumEH[(size_t)(b0 + BT) * (DD * DIN)];
#pragma unroll
            for (int q = 0; q < 5; q++)
                pre[q] = *(const float4*)&src[q * 1024 + t * 4];
        }

        // Z-gen: thread covers 4 batches at its i-pair; stores DUP'D pairs.
        // Batch x/mask loads first (MLP=8), FMA after.
        {
            float m4[4]; float2 xv4[4];
#pragma unroll
            for (int j = 0; j < 4; j++) {
                int b = b0 + bbh * 4 + j;
                m4[j] = __ldg(&mask[(size_t)b * NN + g]);
                xv4[j] = *(const float2*)(x + ((size_t)b * NN + g) * DIN + i2);
            }
#pragma unroll
            for (int j = 0; j < 4; j++) {
                int bb = bbh * 4 + j;
                u64 z = pk2(xv4[j].x * m4[j], xv4[j].y * m4[j]);
#pragma unroll
                for (int d = 0; d < DD; d++) {
                    u64 sv = *(const u64*)&S.sSum[(bb * DD + d) * DIN + i2];
                    f2fma(z, edup[d], sv);
                }
                float2 zf = u2f(z);
                ulonglong2 zz; zz.x = dup2(zf.x); zz.y = dup2(zf.y);
                *(ulonglong2*)&S.sZ[(bb * NT + nt) * DIN + i2] = zz;
            }
        }
        __syncthreads();

        // GEMM: 2 bb x 4 o per thread; pure LDS->FFMA2 inner loop
        u64 acc00, acc01, acc10, acc11;
        {
            ulonglong2 bv = *(const ulonglong2*)&S.sbb[nt * DOUT + o0];
            acc00 = bv.x; acc01 = bv.y; acc10 = bv.x; acc11 = bv.y;
        }
        const u64* zA = &S.sZ[(bb0 * NT + nt) * DIN];
        const u64* zB = &S.sZ[((bb0 + 1) * NT + nt) * DIN];
        const float* wrow = &S.sW[nt * (DIN * DOUT) + o0];
#pragma unroll
        for (int k = 0; k < DIN; k += 2) {
            ulonglong2 w0 = *(const ulonglong2*)(wrow + (size_t)k * DOUT);
            ulonglong2 w1 = *(const ulonglong2*)(wrow + (size_t)(k + 1) * DOUT);
            u64 za0 = zA[k], za1 = zA[k + 1];
            u64 zb0 = zB[k], zb1 = zB[k + 1];
            f2fma(acc00, za0, w0.x); f2fma(acc01, za0, w0.y);
            f2fma(acc10, zb0, w0.x); f2fma(acc11, zb0, w0.y);
            f2fma(acc00, za1, w1.x); f2fma(acc01, za1, w1.y);
            f2fma(acc10, zb1, w1.x); f2fma(acc11, zb1, w1.y);
        }
        {
            float2 p0 = u2f(acc00), p1 = u2f(acc01);
            *(float4*)(out + ((size_t)(b0 + bb0) * NN + node0 + nt) * DOUT + o0) =
                make_float4(p0.x, p0.y, p1.x, p1.y);
            float2 q0 = u2f(acc10), q1 = u2f(acc11);
            *(float4*)(out + ((size_t)(b0 + bb0 + 1) * NN + node0 + nt) * DOUT + o0) =
                make_float4(q0.x, q0.y, q1.x, q1.y);
        }
        __syncthreads();
    }
}

// ---------------------------------------------------------------------------
extern "C" void kernel_launch(void* const* d_in, const int* in_sizes, int n_in,
                              void* d_out, int out_size)
{
    const float* x     = (const float*)d_in[0];
    const float* emb   = (const float*)d_in[1];
    // d_in[2] = poly_coefficients (unused in sprtrelu mode)
    const float* mask  = (const float*)d_in[3];
    const float* wpool = (const float*)d_in[4];
    const float* bpool = (const float*)d_in[5];
    const int*   nodes = (const int*)d_in[6];
    float* out = (float*)d_out;

    cudaFuncSetAttribute(k3_main, cudaFuncAttributeMaxDynamicSharedMemorySize,
                         (int)sizeof(Smem3));

    dim3 g1(K1_CHUNKS, BB);
    k1_partial<<<g1, 256>>>(x, emb, mask, nodes);

    int tot = BB * DD * DIN;
    k2_reduce<<<(tot + 255) / 256, 256>>>();

    k3_main<<<NN / NT, 256, sizeof(Smem3)>>>(x, emb, mask, wpool, bpool, nodes, out);
}

// round 8
// speedup vs baseline: 1.3510x; 1.2501x over previous
#include <cuda_runtime.h>

// Problem constants
#define BB   64      // batch
#define NN   8192    // nodes
#define DIN  64
#define DOUT 64
#define DD   10      // embedding dim
#define CC   4       // clients
#define NPC  2048    // nodes per client

#define K1_CHUNKS 32
#define K1_NODES  (NN / K1_CHUNKS)   // 256 nodes per chunk

#define NT 4    // nodes per block in main kernel
#define BT 32   // batch tile in main kernel (2 iterations)
#define ZPAD 36 // padded bb-row stride for sZ (16B-aligned, conflict-reducing)

typedef unsigned long long u64;

// packed f32x2 helpers (FFMA2/FMUL2 path — ptxas never emits these from C++)
__device__ __forceinline__ u64 pk2(float lo, float hi) {
    u64 r; asm("mov.b64 %0,{%1,%2};" : "=l"(r) : "f"(lo), "f"(hi)); return r;
}
__device__ __forceinline__ u64 dup2(float v) { return pk2(v, v); }
__device__ __forceinline__ void f2fma(u64& d, u64 a, u64 b) {
    asm("fma.rn.f32x2 %0,%1,%2,%3;" : "=l"(d) : "l"(a), "l"(b), "l"(d));
}
__device__ __forceinline__ u64 f2mul(u64 a, u64 b) {
    u64 r; asm("mul.rn.f32x2 %0,%1,%2;" : "=l"(r) : "l"(a), "l"(b)); return r;
}
__device__ __forceinline__ float2 u2f(u64 v) {
    float2 f; asm("mov.b64 {%0,%1},%2;" : "=f"(f.x), "=f"(f.y) : "l"(v)); return f;
}

// Scratch (device globals; no runtime allocation allowed)
__device__ float g_part[BB * K1_CHUNKS * DD * DIN];   // 5.2 MB
__device__ float g_sumEH[BB * DD * DIN];              // 160 KB

// ---------------------------------------------------------------------------
// Kernel 1: partial sum_EH (R6 form — j+=4, best measured at ~50us)
// ---------------------------------------------------------------------------
__global__ __launch_bounds__(256) void k1_partial(
    const float* __restrict__ x, const float* __restrict__ emb,
    const float* __restrict__ mask, const int* __restrict__ nodes_per)
{
    __shared__ u64   s_tE[K1_NODES * DD];   // dup'd relu(E): 20 KB
    __shared__ int   s_g[K1_NODES];          // 1 KB
    __shared__ float s_red[8][DD * DIN];     // 20 KB

    const int t = threadIdx.x;
    const int b = blockIdx.y, chunk = blockIdx.x;
    const int p0 = chunk * K1_NODES;

    for (int p = t; p < K1_NODES; p += 256) s_g[p] = nodes_per[p0 + p];
    __syncthreads();
    for (int e = t; e < K1_NODES * DD; e += 256) {
        int p = e / DD, d = e - p * DD;
        s_tE[e] = dup2(fmaxf(emb[(size_t)s_g[p] * DD + d], 0.f));
    }
    __syncthreads();

    const int w = t >> 5, lane = t & 31;
    const int il = lane & 15, np = lane >> 4;   // i-block, node parity

    u64 acc[DD][2];
#pragma unroll
    for (int d = 0; d < DD; d++) { acc[d][0] = 0ull; acc[d][1] = 0ull; }

    const float* xb = x + (size_t)b * NN * DIN;
    const float* mb = mask + (size_t)b * NN;
    const int base = w * (K1_NODES / 8);   // 32 nodes per warp

#pragma unroll 1
    for (int j = 0; j < K1_NODES / 8; j += 4) {
        int pA = base + j + np, pB = base + j + 2 + np;
        int gA = s_g[pA], gB = s_g[pB];
        float mA = __ldg(&mb[gA]), mB = __ldg(&mb[gB]);
        float4 xA = *(const float4*)(xb + (size_t)gA * DIN + il * 4);
        float4 xB = *(const float4*)(xb + (size_t)gB * DIN + il * 4);

        {
            u64 md = dup2(mA);
            u64 z01 = f2mul(pk2(xA.x, xA.y), md);
            u64 z23 = f2mul(pk2(xA.z, xA.w), md);
            const u64* te = &s_tE[pA * DD];
#pragma unroll
            for (int d = 0; d < DD; d++) {
                u64 e = te[d];
                f2fma(acc[d][0], e, z01);
                f2fma(acc[d][1], e, z23);
            }
        }
        {
            u64 md = dup2(mB);
            u64 z01 = f2mul(pk2(xB.x, xB.y), md);
            u64 z23 = f2mul(pk2(xB.z, xB.w), md);
            const u64* te = &s_tE[pB * DD];
#pragma unroll
            for (int d = 0; d < DD; d++) {
                u64 e = te[d];
                f2fma(acc[d][0], e, z01);
                f2fma(acc[d][1], e, z23);
            }
        }
    }

#pragma unroll
    for (int d = 0; d < DD; d++) {
        float2 v0 = u2f(acc[d][0]), v1 = u2f(acc[d][1]);
        v0.x += __shfl_xor_sync(0xffffffffu, v0.x, 16);
        v0.y += __shfl_xor_sync(0xffffffffu, v0.y, 16);
        v1.x += __shfl_xor_sync(0xffffffffu, v1.x, 16);
        v1.y += __shfl_xor_sync(0xffffffffu, v1.y, 16);
        if (np == 0)
            *(float4*)&s_red[w][d * DIN + il * 4] = make_float4(v0.x, v0.y, v1.x, v1.y);
    }
    __syncthreads();
    for (int di = t; di < DD * DIN; di += 256) {
        float s = 0.f;
#pragma unroll
        for (int w2 = 0; w2 < 8; w2++) s += s_red[w2][di];
        g_part[((size_t)b * K1_CHUNKS + chunk) * (DD * DIN) + di] = s;
    }
}

// ---------------------------------------------------------------------------
// Kernel 2: reduce chunk partials -> g_sumEH[b,d,i]
// ---------------------------------------------------------------------------
__global__ __launch_bounds__(256) void k2_reduce()
{
    int idx = blockIdx.x * 256 + threadIdx.x;
    if (idx >= BB * DD * DIN) return;
    int b = idx / (DD * DIN), di = idx - b * (DD * DIN);
    float s = 0.f;
#pragma unroll
    for (int k = 0; k < K1_CHUNKS; k++)
        s += g_part[((size_t)b * K1_CHUNKS + k) * (DD * DIN) + di];
    g_sumEH[idx] = s;
}

// ---------------------------------------------------------------------------
// Kernel 3: fused main kernel. 256 threads, NT=4, BT=32, 2 CTAs/SM.
// Z stored SCALAR in [nt][k][bb] layout: GEMM reads 48B per 32 MACs.
// sumEH read through L1 (no smem staging).
// ---------------------------------------------------------------------------
struct Smem3 {
    float sW[NT * DIN * DOUT];      // 65536 B  [nt][k][o]
    float sZ[NT * DIN * ZPAD];      // 36864 B  [nt][k][bb(32) pad 36]
    u64   stE[NT * DD];             // dup'd relu(E)
    float sE[NT * DD];
    float sbb[NT * DOUT];
    int   sIdx[NT];
};                                   // ~104 KB -> 2 CTAs/SM

__global__ __launch_bounds__(256, 2) void k3_main(
    const float* __restrict__ x, const float* __restrict__ emb,
    const float* __restrict__ mask, const float* __restrict__ wpool,
    const float* __restrict__ bpool, const int* __restrict__ nodes_per,
    float* __restrict__ out)
{
    extern __shared__ __align__(16) char smem_raw[];
    Smem3& S = *reinterpret_cast<Smem3*>(smem_raw);

    const int t = threadIdx.x;
    const int node0 = blockIdx.x * NT;
    const int c = node0 / NPC;

    if (t < NT) S.sIdx[t] = nodes_per[node0 + t];
    __syncthreads();
    if (t < NT * DD) {
        int nt = t / DD, d = t - nt * DD;
        float v = emb[(size_t)S.sIdx[nt] * DD + d];
        S.sE[t] = v;
        S.stE[t] = dup2(fmaxf(v, 0.f));
    }
    __syncthreads();

    // bias: 256 threads cover NT*DOUT = 256 exactly
    {
        int nt = t >> 6, o = t & 63;
        float s = 0.f;
#pragma unroll
        for (int d = 0; d < DD; d++)
            s = fmaf(S.sE[nt * DD + d], bpool[((size_t)c * DD + d) * DOUT + o], s);
        S.sbb[t] = s;
    }

    // W generation (packed): thread owns 4 consecutive floats per pg (4 pgs).
    const float* wpc = wpool + (size_t)c * DD * DIN * DOUT;
#pragma unroll
    for (int pg = 0; pg < 4; pg++) {
        u64 acc[2][NT];
#pragma unroll
        for (int h = 0; h < 2; h++)
#pragma unroll
            for (int nt = 0; nt < NT; nt++) acc[h][nt] = 0ull;
#pragma unroll
        for (int d = 0; d < DD; d++) {
            ulonglong2 wp = *(const ulonglong2*)&wpc[(size_t)d * (DIN * DOUT) + pg * 1024 + t * 4];
#pragma unroll
            for (int nt = 0; nt < NT; nt++) {
                u64 ed = dup2(S.sE[nt * DD + d]);
                f2fma(acc[0][nt], wp.x, ed);
                f2fma(acc[1][nt], wp.y, ed);
            }
        }
#pragma unroll
        for (int nt = 0; nt < NT; nt++) {
            *(float2*)&S.sW[nt * (DIN * DOUT) + pg * 1024 + t * 4]     = u2f(acc[0][nt]);
            *(float2*)&S.sW[nt * (DIN * DOUT) + pg * 1024 + t * 4 + 2] = u2f(acc[1][nt]);
        }
    }
    __syncthreads();

    // ---- Z-gen mapping: 32 i-pairs x 8 bb-quads ----
    const int i2  = (t & 31) * 2;
    const int bbq = (t >> 5) * 4;

    // ---- GEMM mapping: 8 o-groups x 8 bb-groups per nt ----
    const int ntg = t >> 6;
    const int tid64 = t & 63;
    const int o0  = (tid64 & 7) * 8;
    const int bb0 = (tid64 >> 3) * 4;

    for (int bt = 0; bt < BB / BT; bt++) {
        const int b0 = bt * BT;

        // ---- Z-gen: Z[nt][k][bb] scalar, via L1 reads of g_sumEH ----
#pragma unroll
        for (int nt = 0; nt < NT; nt++) {
            const int g = S.sIdx[nt];
            u64 ed[DD];
#pragma unroll
            for (int d = 0; d < DD; d++) ed[d] = S.stE[nt * DD + d];

            float m4[4]; float2 xv4[4];
#pragma unroll
            for (int j = 0; j < 4; j++) {
                int b = b0 + bbq + j;
                m4[j]  = __ldg(&mask[(size_t)b * NN + g]);
                xv4[j] = *(const float2*)(x + ((size_t)b * NN + g) * DIN + i2);
            }
            float2 zf[4];
#pragma unroll
            for (int j = 0; j < 4; j++) {
                int b = b0 + bbq + j;
                u64 z = pk2(xv4[j].x * m4[j], xv4[j].y * m4[j]);
                const float* se = &g_sumEH[(size_t)b * (DD * DIN) + i2];
#pragma unroll
                for (int d = 0; d < DD; d++) {
                    u64 sv = *(const u64*)(se + d * DIN);
                    f2fma(z, ed[d], sv);
                }
                zf[j] = u2f(z);
            }
            *(float4*)&S.sZ[(nt * DIN + i2)     * ZPAD + bbq] =
                make_float4(zf[0].x, zf[1].x, zf[2].x, zf[3].x);
            *(float4*)&S.sZ[(nt * DIN + i2 + 1) * ZPAD + bbq] =
                make_float4(zf[0].y, zf[1].y, zf[2].y, zf[3].y);
        }
        __syncthreads();

        // ---- GEMM: thread tile 4bb x 8o; 48B LDS per 32 MACs ----
        u64 acc[4][4];
        {
            ulonglong2 bv0 = *(const ulonglong2*)&S.sbb[ntg * DOUT + o0];
            ulonglong2 bv1 = *(const ulonglong2*)&S.sbb[ntg * DOUT + o0 + 4];
#pragma unroll
            for (int j = 0; j < 4; j++) {
                acc[j][0] = bv0.x; acc[j][1] = bv0.y;
                acc[j][2] = bv1.x; acc[j][3] = bv1.y;
            }
        }
        const float* zbase = &S.sZ[ntg * DIN * ZPAD + bb0];
        const float* wbase = &S.sW[ntg * (DIN * DOUT) + o0];
#pragma unroll 8
        for (int k = 0; k < DIN; k++) {
            float4 zv = *(const float4*)(zbase + k * ZPAD);
            ulonglong2 w0 = *(const ulonglong2*)(wbase + (size_t)k * DOUT);
            ulonglong2 w1 = *(const ulonglong2*)(wbase + (size_t)k * DOUT + 4);
            u64 z0 = dup2(zv.x), z1 = dup2(zv.y), z2 = dup2(zv.z), z3 = dup2(zv.w);
            f2fma(acc[0][0], z0, w0.x); f2fma(acc[0][1], z0, w0.y);
            f2fma(acc[0][2], z0, w1.x); f2fma(acc[0][3], z0, w1.y);
            f2fma(acc[1][0], z1, w0.x); f2fma(acc[1][1], z1, w0.y);
            f2fma(acc[1][2], z1, w1.x); f2fma(acc[1][3], z1, w1.y);
            f2fma(acc[2][0], z2, w0.x); f2fma(acc[2][1], z2, w0.y);
            f2fma(acc[2][2], z2, w1.x); f2fma(acc[2][3], z2, w1.y);
            f2fma(acc[3][0], z3, w0.x); f2fma(acc[3][1], z3, w0.y);
            f2fma(acc[3][2], z3, w1.x); f2fma(acc[3][3], z3, w1.y);
        }
#pragma unroll
        for (int j = 0; j < 4; j++) {
            int b = b0 + bb0 + j;
            float* row = out + ((size_t)b * NN + node0 + ntg) * DOUT + o0;
            float2 p0 = u2f(acc[j][0]), p1 = u2f(acc[j][1]);
            float2 p2 = u2f(acc[j][2]), p3 = u2f(acc[j][3]);
            *(float4*)row       = make_float4(p0.x, p0.y, p1.x, p1.y);
            *(float4*)(row + 4) = make_float4(p2.x, p2.y, p3.x, p3.y);
        }
        __syncthreads();
    }
}

// ---------------------------------------------------------------------------
extern "C" void kernel_launch(void* const* d_in, const int* in_sizes, int n_in,
                              void* d_out, int out_size)
{
    const float* x     = (const float*)d_in[0];
    const float* emb   = (const float*)d_in[1];
    // d_in[2] = poly_coefficients (unused in sprtrelu mode)
    const float* mask  = (const float*)d_in[3];
    const float* wpool = (const float*)d_in[4];
    const float* bpool = (const float*)d_in[5];
    const int*   nodes = (const int*)d_in[6];
    float* out = (float*)d_out;

    cudaFuncSetAttribute(k3_main, cudaFuncAttributeMaxDynamicSharedMemorySize,
                         (int)sizeof(Smem3));

    dim3 g1(K1_CHUNKS, BB);
    k1_partial<<<g1, 256>>>(x, emb, mask, nodes);

    int tot = BB * DD * DIN;
    k2_reduce<<<(tot + 255) / 256, 256>>>();

    k3_main<<<NN / NT, 256, sizeof(Smem3)>>>(x, emb, mask, wpool, bpool, nodes, out);
}

// round 9
// speedup vs baseline: 1.3762x; 1.0187x over previous
#include <cuda_runtime.h>

// Problem constants
#define BB   64      // batch
#define NN   8192    // nodes
#define DIN  64
#define DOUT 64
#define DD   10      // embedding dim
#define CC   4       // clients
#define NPC  2048    // nodes per client

#define K1_CHUNKS 32
#define K1_NODES  (NN / K1_CHUNKS)   // 256 nodes per chunk

#define NT 4    // nodes per block in main kernel
#define BT 32   // batch tile in main kernel (2 iterations)
#define ZPAD 36 // padded bb-row stride for sZ

typedef unsigned long long u64;

// packed f32x2 helpers (FFMA2/FMUL2 path — ptxas never emits these from C++)
__device__ __forceinline__ u64 pk2(float lo, float hi) {
    u64 r; asm("mov.b64 %0,{%1,%2};" : "=l"(r) : "f"(lo), "f"(hi)); return r;
}
__device__ __forceinline__ u64 dup2(float v) { return pk2(v, v); }
__device__ __forceinline__ void f2fma(u64& d, u64 a, u64 b) {
    asm("fma.rn.f32x2 %0,%1,%2,%3;" : "=l"(d) : "l"(a), "l"(b), "l"(d));
}
__device__ __forceinline__ u64 f2mul(u64 a, u64 b) {
    u64 r; asm("mul.rn.f32x2 %0,%1,%2;" : "=l"(r) : "l"(a), "l"(b)); return r;
}
__device__ __forceinline__ float2 u2f(u64 v) {
    float2 f; asm("mov.b64 {%0,%1},%2;" : "=f"(f.x), "=f"(f.y) : "l"(v)); return f;
}

// Scratch (device globals; no runtime allocation allowed)
__device__ float g_part[BB * K1_CHUNKS * DD * DIN];   // 5.2 MB
__device__ float g_sumEH[BB * DD * DIN];              // 160 KB

// ---------------------------------------------------------------------------
// Kernel 1: partial sum_EH. One warp covers full Din (32 lanes x float2),
// acc[DD] single u64 each -> 20 acc regs -> 4 CTAs/SM.
// 4 nodes prefetched per step (MLP = 8 loads in flight / thread).
// ---------------------------------------------------------------------------
__global__ __launch_bounds__(256, 4) void k1_partial(
    const float* __restrict__ x, const float* __restrict__ emb,
    const float* __restrict__ mask, const int* __restrict__ nodes_per)
{
    __shared__ u64   s_tE[K1_NODES * DD];   // dup'd relu(E): 20 KB
    __shared__ int   s_g[K1_NODES];          // 1 KB
    __shared__ float s_red[8][DD * DIN];     // 20 KB

    const int t = threadIdx.x;
    const int b = blockIdx.y, chunk = blockIdx.x;
    const int p0 = chunk * K1_NODES;

    for (int p = t; p < K1_NODES; p += 256) s_g[p] = nodes_per[p0 + p];
    __syncthreads();
    for (int e = t; e < K1_NODES * DD; e += 256) {
        int p = e / DD, d = e - p * DD;
        s_tE[e] = dup2(fmaxf(emb[(size_t)s_g[p] * DD + d], 0.f));
    }
    __syncthreads();

    const int w = t >> 5, lane = t & 31;

    u64 acc[DD];
#pragma unroll
    for (int d = 0; d < DD; d++) acc[d] = 0ull;

    const float* xb = x + (size_t)b * NN * DIN + lane * 2;
    const float* mb = mask + (size_t)b * NN;
    const int base = w * (K1_NODES / 8);   // 32 nodes per warp

#pragma unroll 1
    for (int j = 0; j < K1_NODES / 8; j += 4) {
        int g4[4]; float m4[4]; float2 x4[4];
#pragma unroll
        for (int q = 0; q < 4; q++) g4[q] = s_g[base + j + q];
#pragma unroll
        for (int q = 0; q < 4; q++) {
            m4[q] = __ldg(&mb[g4[q]]);
            x4[q] = *(const float2*)(xb + (size_t)g4[q] * DIN);
        }
#pragma unroll
        for (int q = 0; q < 4; q++) {
            u64 z = f2mul(pk2(x4[q].x, x4[q].y), dup2(m4[q]));
            const u64* te = &s_tE[(base + j + q) * DD];
#pragma unroll
            for (int d = 0; d < DD; d++)
                f2fma(acc[d], te[d], z);
        }
    }

#pragma unroll
    for (int d = 0; d < DD; d++)
        *(float2*)&s_red[w][d * DIN + lane * 2] = u2f(acc[d]);
    __syncthreads();
    for (int di = t; di < DD * DIN; di += 256) {
        float s = 0.f;
#pragma unroll
        for (int w2 = 0; w2 < 8; w2++) s += s_red[w2][di];
        g_part[((size_t)b * K1_CHUNKS + chunk) * (DD * DIN) + di] = s;
    }
}

// ---------------------------------------------------------------------------
// Kernel 2: reduce chunk partials -> g_sumEH[b,d,i]
// ---------------------------------------------------------------------------
__global__ __launch_bounds__(256) void k2_reduce()
{
    int idx = blockIdx.x * 256 + threadIdx.x;
    if (idx >= BB * DD * DIN) return;
    int b = idx / (DD * DIN), di = idx - b * (DD * DIN);
    float s = 0.f;
#pragma unroll
    for (int k = 0; k < K1_CHUNKS; k++)
        s += g_part[((size_t)b * K1_CHUNKS + k) * (DD * DIN) + di];
    g_sumEH[idx] = s;
}

// ---------------------------------------------------------------------------
// Kernel 3: fused main kernel. 256 threads, NT=4, BT=32, 2 CTAs/SM.
// Z-gen reorganized: sumEH loaded ONCE per batch (shared across all NT nodes).
// ---------------------------------------------------------------------------
struct Smem3 {
    float sW[NT * DIN * DOUT];      // 65536 B  [nt][k][o]
    float sZ[NT * DIN * ZPAD];      // 36864 B  [nt][k][bb(32) pad 36]
    u64   stE[NT * DD];             // dup'd relu(E)
    float sE[NT * DD];
    float sbb[NT * DOUT];
    int   sIdx[NT];
};                                   // ~104 KB -> 2 CTAs/SM

__global__ __launch_bounds__(256, 2) void k3_main(
    const float* __restrict__ x, const float* __restrict__ emb,
    const float* __restrict__ mask, const float* __restrict__ wpool,
    const float* __restrict__ bpool, const int* __restrict__ nodes_per,
    float* __restrict__ out)
{
    extern __shared__ __align__(16) char smem_raw[];
    Smem3& S = *reinterpret_cast<Smem3*>(smem_raw);

    const int t = threadIdx.x;
    const int node0 = blockIdx.x * NT;
    const int c = node0 / NPC;

    if (t < NT) S.sIdx[t] = nodes_per[node0 + t];
    __syncthreads();
    if (t < NT * DD) {
        int nt = t / DD, d = t - nt * DD;
        float v = emb[(size_t)S.sIdx[nt] * DD + d];
        S.sE[t] = v;
        S.stE[t] = dup2(fmaxf(v, 0.f));
    }
    __syncthreads();

    // bias: 256 threads cover NT*DOUT = 256 exactly
    {
        int nt = t >> 6, o = t & 63;
        float s = 0.f;
#pragma unroll
        for (int d = 0; d < DD; d++)
            s = fmaf(S.sE[nt * DD + d], bpool[((size_t)c * DD + d) * DOUT + o], s);
        S.sbb[t] = s;
    }

    // W generation (packed): thread owns 4 consecutive floats per pg (4 pgs).
    const float* wpc = wpool + (size_t)c * DD * DIN * DOUT;
#pragma unroll
    for (int pg = 0; pg < 4; pg++) {
        u64 acc[2][NT];
#pragma unroll
        for (int h = 0; h < 2; h++)
#pragma unroll
            for (int nt = 0; nt < NT; nt++) acc[h][nt] = 0ull;
#pragma unroll
        for (int d = 0; d < DD; d++) {
            ulonglong2 wp = *(const ulonglong2*)&wpc[(size_t)d * (DIN * DOUT) + pg * 1024 + t * 4];
#pragma unroll
            for (int nt = 0; nt < NT; nt++) {
                u64 ed = dup2(S.sE[nt * DD + d]);
                f2fma(acc[0][nt], wp.x, ed);
                f2fma(acc[1][nt], wp.y, ed);
            }
        }
#pragma unroll
        for (int nt = 0; nt < NT; nt++) {
            *(float2*)&S.sW[nt * (DIN * DOUT) + pg * 1024 + t * 4]     = u2f(acc[0][nt]);
            *(float2*)&S.sW[nt * (DIN * DOUT) + pg * 1024 + t * 4 + 2] = u2f(acc[1][nt]);
        }
    }
    __syncthreads();

    // ---- Z-gen mapping: 32 i-pairs x 8 bb-quads ----
    const int i2  = (t & 31) * 2;
    const int bbq = (t >> 5) * 4;

    // ---- GEMM mapping: 8 o-groups x 8 bb-groups per nt ----
    const int ntg = t >> 6;
    const int tid64 = t & 63;
    const int o0  = (tid64 & 7) * 8;
    const int bb0 = (tid64 >> 3) * 4;

    for (int bt = 0; bt < BB / BT; bt++) {
        const int b0 = bt * BT;

        // ---- Z-gen: j (batch) outer so sumEH is loaded ONCE per batch ----
        float2 zres[NT][4];   // [nt][j]
#pragma unroll
        for (int j = 0; j < 4; j++) {
            const int b = b0 + bbq + j;
            // sumEH slice for this batch (shared by all nt)
            u64 sv[DD];
            const float* se = &g_sumEH[(size_t)b * (DD * DIN) + i2];
#pragma unroll
            for (int d = 0; d < DD; d++) sv[d] = *(const u64*)(se + d * DIN);
            // x/mask for all NT nodes (batched loads)
            float m4[NT]; float2 xv4[NT];
#pragma unroll
            for (int nt = 0; nt < NT; nt++) {
                int g = S.sIdx[nt];
                m4[nt]  = __ldg(&mask[(size_t)b * NN + g]);
                xv4[nt] = *(const float2*)(x + ((size_t)b * NN + g) * DIN + i2);
            }
#pragma unroll
            for (int nt = 0; nt < NT; nt++) {
                u64 z = pk2(xv4[nt].x * m4[nt], xv4[nt].y * m4[nt]);
#pragma unroll
                for (int d = 0; d < DD; d++)
                    f2fma(z, S.stE[nt * DD + d], sv[d]);   // broadcast LDS.64
                zres[nt][j] = u2f(z);
            }
        }
#pragma unroll
        for (int nt = 0; nt < NT; nt++) {
            *(float4*)&S.sZ[(nt * DIN + i2)     * ZPAD + bbq] =
                make_float4(zres[nt][0].x, zres[nt][1].x, zres[nt][2].x, zres[nt][3].x);
            *(float4*)&S.sZ[(nt * DIN + i2 + 1) * ZPAD + bbq] =
                make_float4(zres[nt][0].y, zres[nt][1].y, zres[nt][2].y, zres[nt][3].y);
        }
        __syncthreads();

        // ---- GEMM: thread tile 4bb x 8o; 48B LDS per 32 MACs ----
        u64 acc[4][4];
        {
            ulonglong2 bv0 = *(const ulonglong2*)&S.sbb[ntg * DOUT + o0];
            ulonglong2 bv1 = *(const ulonglong2*)&S.sbb[ntg * DOUT + o0 + 4];
#pragma unroll
            for (int j = 0; j < 4; j++) {
                acc[j][0] = bv0.x; acc[j][1] = bv0.y;
                acc[j][2] = bv1.x; acc[j][3] = bv1.y;
            }
        }
        const float* zbase = &S.sZ[ntg * DIN * ZPAD + bb0];
        const float* wbase = &S.sW[ntg * (DIN * DOUT) + o0];
#pragma unroll 8
        for (int k = 0; k < DIN; k++) {
            float4 zv = *(const float4*)(zbase + k * ZPAD);
            ulonglong2 w0 = *(const ulonglong2*)(wbase + (size_t)k * DOUT);
            ulonglong2 w1 = *(const ulonglong2*)(wbase + (size_t)k * DOUT + 4);
            u64 z0 = dup2(zv.x), z1 = dup2(zv.y), z2 = dup2(zv.z), z3 = dup2(zv.w);
            f2fma(acc[0][0], z0, w0.x); f2fma(acc[0][1], z0, w0.y);
            f2fma(acc[0][2], z0, w1.x); f2fma(acc[0][3], z0, w1.y);
            f2fma(acc[1][0], z1, w0.x); f2fma(acc[1][1], z1, w0.y);
            f2fma(acc[1][2], z1, w1.x); f2fma(acc[1][3], z1, w1.y);
            f2fma(acc[2][0], z2, w0.x); f2fma(acc[2][1], z2, w0.y);
            f2fma(acc[2][2], z2, w1.x); f2fma(acc[2][3], z2, w1.y);
            f2fma(acc[3][0], z3, w0.x); f2fma(acc[3][1], z3, w0.y);
            f2fma(acc[3][2], z3, w1.x); f2fma(acc[3][3], z3, w1.y);
        }
#pragma unroll
        for (int j = 0; j < 4; j++) {
            int b = b0 + bb0 + j;
            float* row = out + ((size_t)b * NN + node0 + ntg) * DOUT + o0;
            float2 p0 = u2f(acc[j][0]), p1 = u2f(acc[j][1]);
            float2 p2 = u2f(acc[j][2]), p3 = u2f(acc[j][3]);
            *(float4*)row       = make_float4(p0.x, p0.y, p1.x, p1.y);
            *(float4*)(row + 4) = make_float4(p2.x, p2.y, p3.x, p3.y);
        }
        __syncthreads();
    }
}

// ---------------------------------------------------------------------------
extern "C" void kernel_launch(void* const* d_in, const int* in_sizes, int n_in,
                              void* d_out, int out_size)
{
    const float* x     = (const float*)d_in[0];
    const float* emb   = (const float*)d_in[1];
    // d_in[2] = poly_coefficients (unused in sprtrelu mode)
    const float* mask  = (const float*)d_in[3];
    const float* wpool = (const float*)d_in[4];
    const float* bpool = (const float*)d_in[5];
    const int*   nodes = (const int*)d_in[6];
    float* out = (float*)d_out;

    cudaFuncSetAttribute(k3_main, cudaFuncAttributeMaxDynamicSharedMemorySize,
                         (int)sizeof(Smem3));

    dim3 g1(K1_CHUNKS, BB);
    k1_partial<<<g1, 256>>>(x, emb, mask, nodes);

    int tot = BB * DD * DIN;
    k2_reduce<<<(tot + 255) / 256, 256>>>();

    k3_main<<<NN / NT, 256, sizeof(Smem3)>>>(x, emb, mask, wpool, bpool, nodes, out);
}